// round 3
// baseline (speedup 1.0000x reference)
#include <cuda_runtime.h>
#include <cstdint>
#include <cstddef>

#define S_LEN 8192
#define HID   1024
#define G4    4096   // 4*HID

// ---------------- scratch (device globals: allocation-free) ----------------
// gates layout: [S][HID][4]  (4 gate values for hidden j contiguous)
__device__ float g_gates[(size_t)S_LEN * G4];   // 128 MB
__device__ float g_yA[(size_t)S_LEN * HID];     // 32 MB: layer outputs ping
__device__ float g_yB[(size_t)S_LEN * HID];     // 32 MB: layer outputs pong
// tagged hidden state: (value, tag) pairs, double-buffered by step parity
__device__ __align__(16) float2 g_hx[2 * HID];

// ---------------- packed f32x2 helpers (sm_103a FFMA2) ----------------
__device__ __forceinline__ void ffma2(unsigned long long& d,
                                      unsigned long long a,
                                      unsigned long long b) {
    asm("fma.rn.f32x2 %0, %1, %2, %0;" : "+l"(d) : "l"(a), "l"(b));
}
__device__ __forceinline__ unsigned long long pack2(float x, float y) {
    unsigned long long r;
    asm("mov.b64 %0, {%1, %2};" : "=l"(r)
        : "r"(__float_as_uint(x)), "r"(__float_as_uint(y)));
    return r;
}
__device__ __forceinline__ float2 unpack2(unsigned long long v) {
    unsigned int lo, hi;
    asm("mov.b64 {%0, %1}, %2;" : "=r"(lo), "=r"(hi) : "l"(v));
    float2 r; r.x = __uint_as_float(lo); r.y = __uint_as_float(hi);
    return r;
}

__device__ __forceinline__ float sigmoidf_(float x) {
    return __fdividef(1.0f, 1.0f + __expf(-x));
}
// fast, overflow-safe tanh: tanh(x) = sign(x) * (1-e)/(1+e), e = exp(-2|x|)
__device__ __forceinline__ float tanhf_(float x) {
    float e = __expf(-2.0f * fabsf(x));
    float r = __fdividef(1.0f - e, 1.0f + e);
    return copysignf(r, x);
}

// volatile L2 float4 load: poll-safe (no CSE/hoist)
__device__ __forceinline__ float4 ldcg4v(const float4* p) {
    float4 v;
    asm volatile("ld.global.cg.v4.f32 {%0,%1,%2,%3}, [%4];"
                 : "=f"(v.x), "=f"(v.y), "=f"(v.z), "=f"(v.w) : "l"(p));
    return v;
}

// ---------------- GEMM: gates[S][HID][4] = X[S,K] @ W[4H,K]^T + b ----------
// BM=BN=128, BK=16, 256 threads, 8x8 microtile, f32x2 packed FMAs.
__global__ __launch_bounds__(256)
void gemm_xwt(const float* __restrict__ Xext, int xsel,
              const float* __restrict__ W, const float* __restrict__ bias,
              int K)
{
    const float* X = (xsel == 0) ? Xext : (xsel == 1 ? g_yA : g_yB);

    __shared__ float a_s[16][128];
    __shared__ float b_s[16][128];

    const int tid = threadIdx.x;
    const int bm = blockIdx.y * 128;
    const int bn = blockIdx.x * 128;
    const int tx = tid & 15;   // 0..15 -> N
    const int ty = tid >> 4;   // 0..15 -> M

    unsigned long long acc[8][4];
#pragma unroll
    for (int i = 0; i < 8; ++i)
#pragma unroll
        for (int jp = 0; jp < 4; ++jp) acc[i][jp] = 0ull;

    for (int k0 = 0; k0 < K; k0 += 16) {
#pragma unroll
        for (int r = 0; r < 2; ++r) {
            int q   = tid + r * 256;      // 0..511 float4 slots
            int row = q >> 2;             // 0..127
            int kq  = (q & 3) << 2;       // 0,4,8,12
            float4 va = *(const float4*)(X + (size_t)(bm + row) * K + k0 + kq);
            a_s[kq + 0][row] = va.x; a_s[kq + 1][row] = va.y;
            a_s[kq + 2][row] = va.z; a_s[kq + 3][row] = va.w;
            float4 vb = *(const float4*)(W + (size_t)(bn + row) * K + k0 + kq);
            b_s[kq + 0][row] = vb.x; b_s[kq + 1][row] = vb.y;
            b_s[kq + 2][row] = vb.z; b_s[kq + 3][row] = vb.w;
        }
        __syncthreads();
#pragma unroll
        for (int kk = 0; kk < 16; ++kk) {
            float4 a0 = *(const float4*)&a_s[kk][ty * 8];
            float4 a1 = *(const float4*)&a_s[kk][ty * 8 + 4];
            float4 b0 = *(const float4*)&b_s[kk][tx * 8];
            float4 b1 = *(const float4*)&b_s[kk][tx * 8 + 4];
            unsigned long long bp0 = pack2(b0.x, b0.y);
            unsigned long long bp1 = pack2(b0.z, b0.w);
            unsigned long long bp2 = pack2(b1.x, b1.y);
            unsigned long long bp3 = pack2(b1.z, b1.w);
            float av[8] = {a0.x, a0.y, a0.z, a0.w, a1.x, a1.y, a1.z, a1.w};
#pragma unroll
            for (int i = 0; i < 8; ++i) {
                unsigned long long ap = pack2(av[i], av[i]);
                ffma2(acc[i][0], ap, bp0);
                ffma2(acc[i][1], ap, bp1);
                ffma2(acc[i][2], ap, bp2);
                ffma2(acc[i][3], ap, bp3);
            }
        }
        __syncthreads();
    }

    // epilogue: scatter into [S][HID][4] interleaved-gate layout
    const int gate = bn >> 10;          // constant per block (bn multiple of 128)
#pragma unroll
    for (int i = 0; i < 8; ++i) {
        size_t row = (size_t)(bm + ty * 8 + i);
#pragma unroll
        for (int jp = 0; jp < 4; ++jp) {
            int col = bn + tx * 8 + jp * 2;
            int jj  = col - (gate << 10);
            float2 v = unpack2(acc[i][jp]);
            g_gates[row * G4 + (size_t)jj * 4 + gate]       = v.x + bias[col];
            g_gates[row * G4 + (size_t)(jj + 1) * 4 + gate] = v.y + bias[col + 1];
        }
    }
}

// ---------------- persistent recurrent scan (one launch per layer) ---------
// 128 blocks x 8 warps; warp w of block b owns hidden index j = b*8+w and
// computes all 4 gate rows for j. w_hh in registers (128 fp32/lane).
// Sync = tagged-h dataflow: producers publish (h, tag) float2 pairs with
// st.global.cg; consumers poll the tagged vectors directly. No barriers,
// fences, or atomics anywhere in the loop.
__global__ __launch_bounds__(256, 1)
void lstm_scan(const float* __restrict__ w_hh, int ysel, int layer)
{
    float* y_out = (ysel == 1) ? g_yA : g_yB;

    const int tid  = threadIdx.x;
    const int lane = tid & 31;
    const int warp = tid >> 5;
    const int j    = blockIdx.x * 8 + warp;    // 0..1023
    const int tagbase = layer * S_LEN + 1;     // tag(t) = tagbase + t, never 0

    // this warp's w_hh slice in registers: w[gate][it] covers
    // k = it*128 + lane*4 .. +3, packed as two f32x2.
    unsigned long long w[4][8][2];
#pragma unroll
    for (int g = 0; g < 4; ++g)
#pragma unroll
        for (int it = 0; it < 8; ++it) {
            union { float4 f4; unsigned long long u[2]; } t;
            t.f4 = *(const float4*)(w_hh + (size_t)(g * HID + j) * HID
                                    + it * 128 + lane * 4);
            w[g][it][0] = t.u[0];
            w[g][it][1] = t.u[1];
        }

    float c = 0.0f;  // cell state (lane 0)

    // prefetch gates for t=0 (one 16B sector per warp)
    float gv = 0.0f;
    if (lane < 4) gv = __ldcg(g_gates + (size_t)0 * G4 + j * 4 + lane);

    for (int t = 0; t < S_LEN; ++t) {
        // prefetch gates for t+1 (DRAM latency hidden behind poll+fma)
        float gnext = 0.0f;
        if (lane < 4 && t + 1 < S_LEN)
            gnext = __ldcg(g_gates + (size_t)(t + 1) * G4 + j * 4 + lane);

        unsigned long long a0 = 0, a1 = 0, a2 = 0, a3 = 0;
        if (t > 0) {
            const float4* hb = (const float4*)g_hx + ((t - 1) & 1) * (HID / 2);
            const int tb = __float_as_int((float)(tagbase + t - 1));
            unsigned done = 0;
            do {
#pragma unroll
                for (int it = 0; it < 8; ++it) {
                    if (!(done & (1u << it))) {
                        // covers h[k..k+3], k = it*128 + lane*4
                        float4 v0 = ldcg4v(hb + it * 64 + lane * 2);
                        float4 v1 = ldcg4v(hb + it * 64 + lane * 2 + 1);
                        if (__float_as_int(v0.y) == tb &&
                            __float_as_int(v0.w) == tb &&
                            __float_as_int(v1.y) == tb &&
                            __float_as_int(v1.w) == tb) {
                            unsigned long long h01 = pack2(v0.x, v0.z);
                            unsigned long long h23 = pack2(v1.x, v1.z);
                            ffma2(a0, h01, w[0][it][0]); ffma2(a0, h23, w[0][it][1]);
                            ffma2(a1, h01, w[1][it][0]); ffma2(a1, h23, w[1][it][1]);
                            ffma2(a2, h01, w[2][it][0]); ffma2(a2, h23, w[2][it][1]);
                            ffma2(a3, h01, w[3][it][0]); ffma2(a3, h23, w[3][it][1]);
                            done |= 1u << it;
                        }
                    }
                }
            } while (__any_sync(0xffffffffu, done != 0xffu));
        }

        float2 p;
        p = unpack2(a0); float si = p.x + p.y;
        p = unpack2(a1); float sf = p.x + p.y;
        p = unpack2(a2); float sg = p.x + p.y;
        p = unpack2(a3); float so = p.x + p.y;
#pragma unroll
        for (int off = 16; off; off >>= 1) {
            si += __shfl_xor_sync(0xffffffffu, si, off);
            sf += __shfl_xor_sync(0xffffffffu, sf, off);
            sg += __shfl_xor_sync(0xffffffffu, sg, off);
            so += __shfl_xor_sync(0xffffffffu, so, off);
        }
        // lanes 0..3 each apply one gate's activation in parallel
        float act = 0.0f;
        if (lane < 4) {
            float gs = (lane == 0) ? si : (lane == 1) ? sf : (lane == 2) ? sg : so;
            float v = gs + gv;
            act = (lane == 2) ? tanhf_(v) : sigmoidf_(v);
        }
        float i_  = __shfl_sync(0xffffffffu, act, 0);
        float f_  = __shfl_sync(0xffffffffu, act, 1);
        float gg_ = __shfl_sync(0xffffffffu, act, 2);
        float o_  = __shfl_sync(0xffffffffu, act, 3);
        if (lane == 0) {
            c = f_ * c + i_ * gg_;
            float hn = o_ * tanhf_(c);
            // publish (value, tag) first — this IS the inter-SM sync
            float2 pub; pub.x = hn; pub.y = (float)(tagbase + t);
            __stcg(&g_hx[(t & 1) * HID + j], pub);
            y_out[(size_t)t * HID + j] = hn;
        }
        gv = gnext;
    }
}

// ---------------- final FC: out = h_last . fc_w + fc_b ---------------------
__global__ void fc_kernel(const float* __restrict__ w,
                          const float* __restrict__ b,
                          float* __restrict__ out)
{
    const float* h = g_yB + (size_t)(S_LEN - 1) * HID;
    const int tid = threadIdx.x;
    float s = 0.0f;
    for (int k = tid; k < HID; k += 256) s += h[k] * w[k];
#pragma unroll
    for (int off = 16; off; off >>= 1) s += __shfl_xor_sync(0xffffffffu, s, off);
    __shared__ float red[8];
    if ((tid & 31) == 0) red[tid >> 5] = s;
    __syncthreads();
    if (tid == 0) {
        float tot = 0.0f;
#pragma unroll
        for (int i = 0; i < 8; ++i) tot += red[i];
        out[0] = tot + b[0];
    }
}

// ---------------- launch ----------------------------------------------------
extern "C" void kernel_launch(void* const* d_in, const int* in_sizes, int n_in,
                              void* d_out, int out_size)
{
    (void)in_sizes; (void)n_in; (void)out_size;
    const float* seq   = (const float*)d_in[0];
    const float* w_ih0 = (const float*)d_in[1];
    const float* w_hh0 = (const float*)d_in[2];
    const float* b0    = (const float*)d_in[3];
    const float* w_ih1 = (const float*)d_in[4];
    const float* w_hh1 = (const float*)d_in[5];
    const float* b1    = (const float*)d_in[6];
    const float* w_ih2 = (const float*)d_in[7];
    const float* w_hh2 = (const float*)d_in[8];
    const float* b2    = (const float*)d_in[9];
    const float* w_ih3 = (const float*)d_in[10];
    const float* w_hh3 = (const float*)d_in[11];
    const float* b3    = (const float*)d_in[12];
    const float* fc_w  = (const float*)d_in[13];
    const float* fc_b  = (const float*)d_in[14];
    float* out = (float*)d_out;

    dim3 ggrid(G4 / 128, S_LEN / 128);

    // layer 0
    gemm_xwt<<<ggrid, 256>>>(seq, 0, w_ih0, b0, 256);
    lstm_scan<<<128, 256>>>(w_hh0, 1, 0);   // -> g_yA
    // layer 1
    gemm_xwt<<<ggrid, 256>>>(nullptr, 1, w_ih1, b1, HID);
    lstm_scan<<<128, 256>>>(w_hh1, 2, 1);   // -> g_yB
    // layer 2
    gemm_xwt<<<ggrid, 256>>>(nullptr, 2, w_ih2, b2, HID);
    lstm_scan<<<128, 256>>>(w_hh2, 1, 2);   // -> g_yA
    // layer 3
    gemm_xwt<<<ggrid, 256>>>(nullptr, 1, w_ih3, b3, HID);
    lstm_scan<<<128, 256>>>(w_hh3, 2, 3);   // -> g_yB
    // head
    fc_kernel<<<1, 256>>>(fc_w, fc_b, out);
}

// round 4
// speedup vs baseline: 2.7728x; 2.7728x over previous
#include <cuda_runtime.h>
#include <cstdint>
#include <cstddef>

#define S_LEN 8192
#define HID   1024
#define G4    4096   // 4*HID

// ---------------- scratch (device globals: allocation-free) ----------------
// gates layout: [S][HID][4]  (4 gate values for hidden j contiguous)
__device__ float g_gates[(size_t)S_LEN * G4];   // 128 MB
__device__ float g_yA[(size_t)S_LEN * HID];     // 32 MB: layer outputs ping
__device__ float g_yB[(size_t)S_LEN * HID];     // 32 MB: layer outputs pong
// tagged hidden state: (value, tag) pairs, double-buffered by step parity
__device__ __align__(16) float2 g_hx[2 * HID];

// ---------------- packed f32x2 helpers (sm_103a FFMA2) ----------------
__device__ __forceinline__ void ffma2(unsigned long long& d,
                                      unsigned long long a,
                                      unsigned long long b) {
    asm("fma.rn.f32x2 %0, %1, %2, %0;" : "+l"(d) : "l"(a), "l"(b));
}
__device__ __forceinline__ unsigned long long pack2(float x, float y) {
    unsigned long long r;
    asm("mov.b64 %0, {%1, %2};" : "=l"(r)
        : "r"(__float_as_uint(x)), "r"(__float_as_uint(y)));
    return r;
}
__device__ __forceinline__ float2 unpack2(unsigned long long v) {
    unsigned int lo, hi;
    asm("mov.b64 {%0, %1}, %2;" : "=r"(lo), "=r"(hi) : "l"(v));
    float2 r; r.x = __uint_as_float(lo); r.y = __uint_as_float(hi);
    return r;
}

__device__ __forceinline__ float sigmoidf_(float x) {
    return __fdividef(1.0f, 1.0f + __expf(-x));
}
// fast, overflow-safe tanh: tanh(x) = sign(x) * (1-e)/(1+e), e = exp(-2|x|)
__device__ __forceinline__ float tanhf_(float x) {
    float e = __expf(-2.0f * fabsf(x));
    float r = __fdividef(1.0f - e, 1.0f + e);
    return copysignf(r, x);
}

// volatile L2 float4 load: poll-safe (no CSE/hoist)
__device__ __forceinline__ float4 ldcg4v(const float4* p) {
    float4 v;
    asm volatile("ld.global.cg.v4.f32 {%0,%1,%2,%3}, [%4];"
                 : "=f"(v.x), "=f"(v.y), "=f"(v.z), "=f"(v.w) : "l"(p));
    return v;
}

// ---------------- GEMM: gates[S][HID][4] = X[S,K] @ W[4H,K]^T + b ----------
// BM=BN=128, BK=16, 256 threads, 8x8 microtile, f32x2 packed FMAs.
__global__ __launch_bounds__(256)
void gemm_xwt(const float* __restrict__ Xext, int xsel,
              const float* __restrict__ W, const float* __restrict__ bias,
              int K)
{
    const float* X = (xsel == 0) ? Xext : (xsel == 1 ? g_yA : g_yB);

    __shared__ float a_s[16][128];
    __shared__ float b_s[16][128];

    const int tid = threadIdx.x;
    const int bm = blockIdx.y * 128;
    const int bn = blockIdx.x * 128;
    const int tx = tid & 15;   // 0..15 -> N
    const int ty = tid >> 4;   // 0..15 -> M

    unsigned long long acc[8][4];
#pragma unroll
    for (int i = 0; i < 8; ++i)
#pragma unroll
        for (int jp = 0; jp < 4; ++jp) acc[i][jp] = 0ull;

    for (int k0 = 0; k0 < K; k0 += 16) {
#pragma unroll
        for (int r = 0; r < 2; ++r) {
            int q   = tid + r * 256;      // 0..511 float4 slots
            int row = q >> 2;             // 0..127
            int kq  = (q & 3) << 2;       // 0,4,8,12
            float4 va = *(const float4*)(X + (size_t)(bm + row) * K + k0 + kq);
            a_s[kq + 0][row] = va.x; a_s[kq + 1][row] = va.y;
            a_s[kq + 2][row] = va.z; a_s[kq + 3][row] = va.w;
            float4 vb = *(const float4*)(W + (size_t)(bn + row) * K + k0 + kq);
            b_s[kq + 0][row] = vb.x; b_s[kq + 1][row] = vb.y;
            b_s[kq + 2][row] = vb.z; b_s[kq + 3][row] = vb.w;
        }
        __syncthreads();
#pragma unroll
        for (int kk = 0; kk < 16; ++kk) {
            float4 a0 = *(const float4*)&a_s[kk][ty * 8];
            float4 a1 = *(const float4*)&a_s[kk][ty * 8 + 4];
            float4 b0 = *(const float4*)&b_s[kk][tx * 8];
            float4 b1 = *(const float4*)&b_s[kk][tx * 8 + 4];
            unsigned long long bp0 = pack2(b0.x, b0.y);
            unsigned long long bp1 = pack2(b0.z, b0.w);
            unsigned long long bp2 = pack2(b1.x, b1.y);
            unsigned long long bp3 = pack2(b1.z, b1.w);
            float av[8] = {a0.x, a0.y, a0.z, a0.w, a1.x, a1.y, a1.z, a1.w};
#pragma unroll
            for (int i = 0; i < 8; ++i) {
                unsigned long long ap = pack2(av[i], av[i]);
                ffma2(acc[i][0], ap, bp0);
                ffma2(acc[i][1], ap, bp1);
                ffma2(acc[i][2], ap, bp2);
                ffma2(acc[i][3], ap, bp3);
            }
        }
        __syncthreads();
    }

    // epilogue: scatter into [S][HID][4] interleaved-gate layout
    const int gate = bn >> 10;          // constant per block (bn multiple of 128)
#pragma unroll
    for (int i = 0; i < 8; ++i) {
        size_t row = (size_t)(bm + ty * 8 + i);
#pragma unroll
        for (int jp = 0; jp < 4; ++jp) {
            int col = bn + tx * 8 + jp * 2;
            int jj  = col - (gate << 10);
            float2 v = unpack2(acc[i][jp]);
            g_gates[row * G4 + (size_t)jj * 4 + gate]       = v.x + bias[col];
            g_gates[row * G4 + (size_t)(jj + 1) * 4 + gate] = v.y + bias[col + 1];
        }
    }
}

// ---------------- persistent recurrent scan (one launch per layer) ---------
// 128 blocks x 8 warps; warp w of block b owns hidden index j = b*8+w and
// computes all 4 gate rows for j. w_hh in registers (128 fp32/lane).
//
// Inter-SM sync = tagged-h dataflow, but h is staged ONCE per block into
// double-buffered shared memory: 256 staging threads each poll 4 tagged
// (value,tag) pairs from L2 and deposit values into SMEM. Compute warps read
// h from SMEM (conflict-free LDS.128). One __syncthreads per step.
// Global h traffic: 128 blocks * 8KB = 1MB/step (vs 8MB+ when every warp
// polled the full vector).
__global__ __launch_bounds__(256, 1)
void lstm_scan(const float* __restrict__ w_hh, int ysel, int layer)
{
    float* y_out = (ysel == 1) ? g_yA : g_yB;

    __shared__ __align__(16) float sm_h[2][HID];   // double-buffered staged h

    const int tid  = threadIdx.x;
    const int lane = tid & 31;
    const int warp = tid >> 5;
    const int j    = blockIdx.x * 8 + warp;    // 0..1023
    const int tagbase = layer * S_LEN + 1;     // tag(t) = tagbase + t, never 0

    // this warp's w_hh slice in registers: w[gate][it] covers
    // k = it*128 + lane*4 .. +3, packed as two f32x2.
    unsigned long long w[4][8][2];
#pragma unroll
    for (int g = 0; g < 4; ++g)
#pragma unroll
        for (int it = 0; it < 8; ++it) {
            union { float4 f4; unsigned long long u[2]; } t;
            t.f4 = *(const float4*)(w_hh + (size_t)(g * HID + j) * HID
                                    + it * 128 + lane * 4);
            w[g][it][0] = t.u[0];
            w[g][it][1] = t.u[1];
        }

    float c = 0.0f;  // cell state (lane 0)

    // gates prefetch pipeline, 2 steps deep (one 16B sector per warp/step)
    float gv = 0.0f, g1 = 0.0f;
    if (lane < 4) {
        gv = __ldcg(g_gates + (size_t)0 * G4 + j * 4 + lane);
        g1 = __ldcg(g_gates + (size_t)1 * G4 + j * 4 + lane);
    }

    for (int t = 0; t < S_LEN; ++t) {
        // prefetch gates for t+2
        float g2 = 0.0f;
        if (lane < 4 && t + 2 < S_LEN)
            g2 = __ldcg(g_gates + (size_t)(t + 2) * G4 + j * 4 + lane);

        if (t > 0) {
            // ---- stage h(t-1): all 256 threads poll 4 tagged pairs each ----
            const int par = (t - 1) & 1;
            const float4* hb = (const float4*)g_hx + par * (HID / 2) + tid * 2;
            const int tb = __float_as_int((float)(tagbase + t - 1));
            float4 v0, v1;
            bool ok0 = false, ok1 = false;
            do {
                if (!ok0) {
                    v0 = ldcg4v(hb);
                    ok0 = (__float_as_int(v0.y) == tb) &
                          (__float_as_int(v0.w) == tb);
                }
                if (!ok1) {
                    v1 = ldcg4v(hb + 1);
                    ok1 = (__float_as_int(v1.y) == tb) &
                          (__float_as_int(v1.w) == tb);
                }
            } while (!(ok0 && ok1));
            float* hs = sm_h[par] + tid * 4;
            hs[0] = v0.x; hs[1] = v0.z; hs[2] = v1.x; hs[3] = v1.z;
        }
        __syncthreads();

        unsigned long long a0 = 0, a1 = 0, a2 = 0, a3 = 0;
        if (t > 0) {
            const float* hs = sm_h[(t - 1) & 1];
#pragma unroll
            for (int it = 0; it < 8; ++it) {
                union { float4 f4; unsigned long long u[2]; } hv;
                hv.f4 = *(const float4*)(hs + it * 128 + lane * 4);
                ffma2(a0, hv.u[0], w[0][it][0]); ffma2(a0, hv.u[1], w[0][it][1]);
                ffma2(a1, hv.u[0], w[1][it][0]); ffma2(a1, hv.u[1], w[1][it][1]);
                ffma2(a2, hv.u[0], w[2][it][0]); ffma2(a2, hv.u[1], w[2][it][1]);
                ffma2(a3, hv.u[0], w[3][it][0]); ffma2(a3, hv.u[1], w[3][it][1]);
            }
        }

        float2 p;
        p = unpack2(a0); float si = p.x + p.y;
        p = unpack2(a1); float sf = p.x + p.y;
        p = unpack2(a2); float sg = p.x + p.y;
        p = unpack2(a3); float so = p.x + p.y;
#pragma unroll
        for (int off = 16; off; off >>= 1) {
            si += __shfl_xor_sync(0xffffffffu, si, off);
            sf += __shfl_xor_sync(0xffffffffu, sf, off);
            sg += __shfl_xor_sync(0xffffffffu, sg, off);
            so += __shfl_xor_sync(0xffffffffu, so, off);
        }
        // lanes 0..3 each apply one gate's activation in parallel
        float act = 0.0f;
        if (lane < 4) {
            float gs = (lane == 0) ? si : (lane == 1) ? sf : (lane == 2) ? sg : so;
            float v = gs + gv;
            act = (lane == 2) ? tanhf_(v) : sigmoidf_(v);
        }
        float i_  = __shfl_sync(0xffffffffu, act, 0);
        float f_  = __shfl_sync(0xffffffffu, act, 1);
        float gg_ = __shfl_sync(0xffffffffu, act, 2);
        float o_  = __shfl_sync(0xffffffffu, act, 3);
        if (lane == 0) {
            c = f_ * c + i_ * gg_;
            float hn = o_ * tanhf_(c);
            // publish (value, tag) — this IS the inter-SM sync
            float2 pub; pub.x = hn; pub.y = (float)(tagbase + t);
            __stcg(&g_hx[(t & 1) * HID + j], pub);
            y_out[(size_t)t * HID + j] = hn;
        }
        gv = g1; g1 = g2;
    }
}

// ---------------- final FC: out = h_last . fc_w + fc_b ---------------------
__global__ void fc_kernel(const float* __restrict__ w,
                          const float* __restrict__ b,
                          float* __restrict__ out)
{
    const float* h = g_yB + (size_t)(S_LEN - 1) * HID;
    const int tid = threadIdx.x;
    float s = 0.0f;
    for (int k = tid; k < HID; k += 256) s += h[k] * w[k];
#pragma unroll
    for (int off = 16; off; off >>= 1) s += __shfl_xor_sync(0xffffffffu, s, off);
    __shared__ float red[8];
    if ((tid & 31) == 0) red[tid >> 5] = s;
    __syncthreads();
    if (tid == 0) {
        float tot = 0.0f;
#pragma unroll
        for (int i = 0; i < 8; ++i) tot += red[i];
        out[0] = tot + b[0];
    }
}

// ---------------- launch ----------------------------------------------------
extern "C" void kernel_launch(void* const* d_in, const int* in_sizes, int n_in,
                              void* d_out, int out_size)
{
    (void)in_sizes; (void)n_in; (void)out_size;
    const float* seq   = (const float*)d_in[0];
    const float* w_ih0 = (const float*)d_in[1];
    const float* w_hh0 = (const float*)d_in[2];
    const float* b0    = (const float*)d_in[3];
    const float* w_ih1 = (const float*)d_in[4];
    const float* w_hh1 = (const float*)d_in[5];
    const float* b1    = (const float*)d_in[6];
    const float* w_ih2 = (const float*)d_in[7];
    const float* w_hh2 = (const float*)d_in[8];
    const float* b2    = (const float*)d_in[9];
    const float* w_ih3 = (const float*)d_in[10];
    const float* w_hh3 = (const float*)d_in[11];
    const float* b3    = (const float*)d_in[12];
    const float* fc_w  = (const float*)d_in[13];
    const float* fc_b  = (const float*)d_in[14];
    float* out = (float*)d_out;

    dim3 ggrid(G4 / 128, S_LEN / 128);

    // layer 0
    gemm_xwt<<<ggrid, 256>>>(seq, 0, w_ih0, b0, 256);
    lstm_scan<<<128, 256>>>(w_hh0, 1, 0);   // -> g_yA
    // layer 1
    gemm_xwt<<<ggrid, 256>>>(nullptr, 1, w_ih1, b1, HID);
    lstm_scan<<<128, 256>>>(w_hh1, 2, 1);   // -> g_yB
    // layer 2
    gemm_xwt<<<ggrid, 256>>>(nullptr, 2, w_ih2, b2, HID);
    lstm_scan<<<128, 256>>>(w_hh2, 1, 2);   // -> g_yA
    // layer 3
    gemm_xwt<<<ggrid, 256>>>(nullptr, 1, w_ih3, b3, HID);
    lstm_scan<<<128, 256>>>(w_hh3, 2, 3);   // -> g_yB
    // head
    fc_kernel<<<1, 256>>>(fc_w, fc_b, out);
}

// round 5
// speedup vs baseline: 4.0230x; 1.4509x over previous
#include <cuda_runtime.h>
#include <cstdint>
#include <cstddef>

#define S_LEN 8192
#define HID   1024
#define G4    4096   // 4*HID

// ---------------- scratch (device globals: allocation-free) ----------------
// gates layout: [S][HID][4]  (4 gate values for hidden j contiguous)
__device__ float g_gates[(size_t)S_LEN * G4];   // 128 MB
__device__ float g_yA[(size_t)S_LEN * HID];     // 32 MB: layer outputs ping
__device__ float g_yB[(size_t)S_LEN * HID];     // 32 MB: layer outputs pong
// tagged hidden state: (value, tag) pairs, double-buffered by step parity
__device__ __align__(16) float2 g_hx[2 * HID];

// ---------------- packed f32x2 helpers (sm_103a FFMA2) ----------------
__device__ __forceinline__ void ffma2(unsigned long long& d,
                                      unsigned long long a,
                                      unsigned long long b) {
    asm("fma.rn.f32x2 %0, %1, %2, %0;" : "+l"(d) : "l"(a), "l"(b));
}
__device__ __forceinline__ unsigned long long pack2(float x, float y) {
    unsigned long long r;
    asm("mov.b64 %0, {%1, %2};" : "=l"(r)
        : "r"(__float_as_uint(x)), "r"(__float_as_uint(y)));
    return r;
}
__device__ __forceinline__ float2 unpack2(unsigned long long v) {
    unsigned int lo, hi;
    asm("mov.b64 {%0, %1}, %2;" : "=r"(lo), "=r"(hi) : "l"(v));
    float2 r; r.x = __uint_as_float(lo); r.y = __uint_as_float(hi);
    return r;
}

__device__ __forceinline__ float sigmoidf_(float x) {
    return __fdividef(1.0f, 1.0f + __expf(-x));
}
// fast, overflow-safe tanh: tanh(x) = sign(x) * (1-e)/(1+e), e = exp(-2|x|)
__device__ __forceinline__ float tanhf_(float x) {
    float e = __expf(-2.0f * fabsf(x));
    float r = __fdividef(1.0f - e, 1.0f + e);
    return copysignf(r, x);
}

// volatile L2 float4 load: poll-safe (no CSE/hoist)
__device__ __forceinline__ float4 ldcg4v(const float4* p) {
    float4 v;
    asm volatile("ld.global.cg.v4.f32 {%0,%1,%2,%3}, [%4];"
                 : "=f"(v.x), "=f"(v.y), "=f"(v.z), "=f"(v.w) : "l"(p));
    return v;
}

// ---------------- GEMM: gates[S][HID][4] = X[S,K] @ W[4H,K]^T + b ----------
// BM=BN=128, BK=16, 256 threads, 8x8 microtile, f32x2 packed FMAs.
__global__ __launch_bounds__(256)
void gemm_xwt(const float* __restrict__ Xext, int xsel,
              const float* __restrict__ W, const float* __restrict__ bias,
              int K)
{
    const float* X = (xsel == 0) ? Xext : (xsel == 1 ? g_yA : g_yB);

    __shared__ float a_s[16][128];
    __shared__ float b_s[16][128];

    const int tid = threadIdx.x;
    const int bm = blockIdx.y * 128;
    const int bn = blockIdx.x * 128;
    const int tx = tid & 15;   // 0..15 -> N
    const int ty = tid >> 4;   // 0..15 -> M

    unsigned long long acc[8][4];
#pragma unroll
    for (int i = 0; i < 8; ++i)
#pragma unroll
        for (int jp = 0; jp < 4; ++jp) acc[i][jp] = 0ull;

    for (int k0 = 0; k0 < K; k0 += 16) {
#pragma unroll
        for (int r = 0; r < 2; ++r) {
            int q   = tid + r * 256;      // 0..511 float4 slots
            int row = q >> 2;             // 0..127
            int kq  = (q & 3) << 2;       // 0,4,8,12
            float4 va = *(const float4*)(X + (size_t)(bm + row) * K + k0 + kq);
            a_s[kq + 0][row] = va.x; a_s[kq + 1][row] = va.y;
            a_s[kq + 2][row] = va.z; a_s[kq + 3][row] = va.w;
            float4 vb = *(const float4*)(W + (size_t)(bn + row) * K + k0 + kq);
            b_s[kq + 0][row] = vb.x; b_s[kq + 1][row] = vb.y;
            b_s[kq + 2][row] = vb.z; b_s[kq + 3][row] = vb.w;
        }
        __syncthreads();
#pragma unroll
        for (int kk = 0; kk < 16; ++kk) {
            float4 a0 = *(const float4*)&a_s[kk][ty * 8];
            float4 a1 = *(const float4*)&a_s[kk][ty * 8 + 4];
            float4 b0 = *(const float4*)&b_s[kk][tx * 8];
            float4 b1 = *(const float4*)&b_s[kk][tx * 8 + 4];
            unsigned long long bp0 = pack2(b0.x, b0.y);
            unsigned long long bp1 = pack2(b0.z, b0.w);
            unsigned long long bp2 = pack2(b1.x, b1.y);
            unsigned long long bp3 = pack2(b1.z, b1.w);
            float av[8] = {a0.x, a0.y, a0.z, a0.w, a1.x, a1.y, a1.z, a1.w};
#pragma unroll
            for (int i = 0; i < 8; ++i) {
                unsigned long long ap = pack2(av[i], av[i]);
                ffma2(acc[i][0], ap, bp0);
                ffma2(acc[i][1], ap, bp1);
                ffma2(acc[i][2], ap, bp2);
                ffma2(acc[i][3], ap, bp3);
            }
        }
        __syncthreads();
    }

    // epilogue: scatter into [S][HID][4] interleaved-gate layout
    const int gate = bn >> 10;          // constant per block (bn multiple of 128)
#pragma unroll
    for (int i = 0; i < 8; ++i) {
        size_t row = (size_t)(bm + ty * 8 + i);
#pragma unroll
        for (int jp = 0; jp < 4; ++jp) {
            int col = bn + tx * 8 + jp * 2;
            int jj  = col - (gate << 10);
            float2 v = unpack2(acc[i][jp]);
            g_gates[row * G4 + (size_t)jj * 4 + gate]       = v.x + bias[col];
            g_gates[row * G4 + (size_t)(jj + 1) * 4 + gate] = v.y + bias[col + 1];
        }
    }
}

// ---------------- persistent recurrent scan (one launch per layer) ---------
// 128 blocks x 8 warps; warp w of block b owns hidden index j = b*8+w and
// computes all 4 gate rows for j. w_hh in registers (128 fp32/lane).
//
// Inter-SM sync = tagged-h dataflow staged through SMEM, two-phase:
//   poll+stage h[0:512] -> bar -> GEMV half0 (overlaps half1 landing in L2)
//   poll+stage h[512:1024] -> bar -> GEMV half1 -> reduce -> epilogue
// Failed polls back off with __nanosleep so retries don't saturate L2/LSU
// and delay the producers' own stores.
__global__ __launch_bounds__(256, 1)
void lstm_scan(const float* __restrict__ w_hh, int ysel, int layer)
{
    float* y_out = (ysel == 1) ? g_yA : g_yB;

    __shared__ __align__(16) float sm_h[2][HID];   // double-buffered staged h

    const int tid  = threadIdx.x;
    const int lane = tid & 31;
    const int warp = tid >> 5;
    const int j    = blockIdx.x * 8 + warp;    // 0..1023
    const int tagbase = layer * S_LEN + 1;     // tag(t) = tagbase + t, never 0

    // this warp's w_hh slice in registers: w[gate][it] covers
    // k = it*128 + lane*4 .. +3, packed as two f32x2.
    unsigned long long w[4][8][2];
#pragma unroll
    for (int g = 0; g < 4; ++g)
#pragma unroll
        for (int it = 0; it < 8; ++it) {
            union { float4 f4; unsigned long long u[2]; } t;
            t.f4 = *(const float4*)(w_hh + (size_t)(g * HID + j) * HID
                                    + it * 128 + lane * 4);
            w[g][it][0] = t.u[0];
            w[g][it][1] = t.u[1];
        }

    float c = 0.0f;  // cell state (redundant in all lanes)

    // gates prefetch pipeline, 2 steps deep. Warp-uniform float4 load:
    // every lane gets all 4 gate values for its j (same 16B sector).
    const float4* gbase = (const float4*)g_gates + j;   // stride G4/4 per step
    float4 gq  = __ldcg(gbase + (size_t)0 * HID);
    float4 gq1 = __ldcg(gbase + (size_t)1 * HID);

    for (int t = 0; t < S_LEN; ++t) {
        // prefetch gates for t+2
        float4 gq2 = make_float4(0.f, 0.f, 0.f, 0.f);
        if (t + 2 < S_LEN) gq2 = __ldcg(gbase + (size_t)(t + 2) * HID);

        const int par = (t - 1) & 1;
        const int tb  = __float_as_int((float)(tagbase + t - 1));
        const float4* hb = (const float4*)g_hx + par * (HID / 2);

        unsigned long long a0 = 0, a1 = 0, a2 = 0, a3 = 0;

        if (t > 0) {
            // ---- phase A: stage h[0:512] (thread tid covers j=2tid,2tid+1)
            float4 v = ldcg4v(hb + tid);
            while (__float_as_int(v.y) != tb || __float_as_int(v.w) != tb) {
                __nanosleep(40);
                v = ldcg4v(hb + tid);
            }
            sm_h[par][2 * tid]     = v.x;
            sm_h[par][2 * tid + 1] = v.z;
        }
        __syncthreads();

        if (t > 0) {
            // ---- GEMV half0 (k = 0..511) while half1 lands in L2 ----
            const float* hs = sm_h[par];
#pragma unroll
            for (int it = 0; it < 4; ++it) {
                union { float4 f4; unsigned long long u[2]; } hv;
                hv.f4 = *(const float4*)(hs + it * 128 + lane * 4);
                ffma2(a0, hv.u[0], w[0][it][0]); ffma2(a0, hv.u[1], w[0][it][1]);
                ffma2(a1, hv.u[0], w[1][it][0]); ffma2(a1, hv.u[1], w[1][it][1]);
                ffma2(a2, hv.u[0], w[2][it][0]); ffma2(a2, hv.u[1], w[2][it][1]);
                ffma2(a3, hv.u[0], w[3][it][0]); ffma2(a3, hv.u[1], w[3][it][1]);
            }
            // ---- phase B: stage h[512:1024] ----
            float4 v = ldcg4v(hb + 256 + tid);
            while (__float_as_int(v.y) != tb || __float_as_int(v.w) != tb) {
                __nanosleep(40);
                v = ldcg4v(hb + 256 + tid);
            }
            sm_h[par][512 + 2 * tid] = v.x;
            sm_h[par][513 + 2 * tid] = v.z;
        }
        __syncthreads();

        if (t > 0) {
            // ---- GEMV half1 (k = 512..1023) ----
            const float* hs = sm_h[par];
#pragma unroll
            for (int it = 4; it < 8; ++it) {
                union { float4 f4; unsigned long long u[2]; } hv;
                hv.f4 = *(const float4*)(hs + it * 128 + lane * 4);
                ffma2(a0, hv.u[0], w[0][it][0]); ffma2(a0, hv.u[1], w[0][it][1]);
                ffma2(a1, hv.u[0], w[1][it][0]); ffma2(a1, hv.u[1], w[1][it][1]);
                ffma2(a2, hv.u[0], w[2][it][0]); ffma2(a2, hv.u[1], w[2][it][1]);
                ffma2(a3, hv.u[0], w[3][it][0]); ffma2(a3, hv.u[1], w[3][it][1]);
            }
        }

        float2 p;
        p = unpack2(a0); float si = p.x + p.y;
        p = unpack2(a1); float sf = p.x + p.y;
        p = unpack2(a2); float sg = p.x + p.y;
        p = unpack2(a3); float so = p.x + p.y;
#pragma unroll
        for (int off = 16; off; off >>= 1) {
            si += __shfl_xor_sync(0xffffffffu, si, off);
            sf += __shfl_xor_sync(0xffffffffu, sf, off);
            sg += __shfl_xor_sync(0xffffffffu, sg, off);
            so += __shfl_xor_sync(0xffffffffu, so, off);
        }
        // butterfly left full sums in every lane; all lanes compute the
        // epilogue redundantly (no broadcast shuffles on the chain)
        float i_  = sigmoidf_(si + gq.x);
        float f_  = sigmoidf_(sf + gq.y);
        float gg_ = tanhf_  (sg + gq.z);
        float o_  = sigmoidf_(so + gq.w);
        c = f_ * c + i_ * gg_;
        float hn = o_ * tanhf_(c);
        if (lane == 0) {
            // publish (value, tag) FIRST — this is the inter-SM sync
            float2 pub; pub.x = hn; pub.y = (float)(tagbase + t);
            __stcg(&g_hx[(t & 1) * HID + j], pub);
            y_out[(size_t)t * HID + j] = hn;
        }
        gq = gq1; gq1 = gq2;
    }
}

// ---------------- final FC: out = h_last . fc_w + fc_b ---------------------
__global__ void fc_kernel(const float* __restrict__ w,
                          const float* __restrict__ b,
                          float* __restrict__ out)
{
    const float* h = g_yB + (size_t)(S_LEN - 1) * HID;
    const int tid = threadIdx.x;
    float s = 0.0f;
    for (int k = tid; k < HID; k += 256) s += h[k] * w[k];
#pragma unroll
    for (int off = 16; off; off >>= 1) s += __shfl_xor_sync(0xffffffffu, s, off);
    __shared__ float red[8];
    if ((tid & 31) == 0) red[tid >> 5] = s;
    __syncthreads();
    if (tid == 0) {
        float tot = 0.0f;
#pragma unroll
        for (int i = 0; i < 8; ++i) tot += red[i];
        out[0] = tot + b[0];
    }
}

// ---------------- launch ----------------------------------------------------
extern "C" void kernel_launch(void* const* d_in, const int* in_sizes, int n_in,
                              void* d_out, int out_size)
{
    (void)in_sizes; (void)n_in; (void)out_size;
    const float* seq   = (const float*)d_in[0];
    const float* w_ih0 = (const float*)d_in[1];
    const float* w_hh0 = (const float*)d_in[2];
    const float* b0    = (const float*)d_in[3];
    const float* w_ih1 = (const float*)d_in[4];
    const float* w_hh1 = (const float*)d_in[5];
    const float* b1    = (const float*)d_in[6];
    const float* w_ih2 = (const float*)d_in[7];
    const float* w_hh2 = (const float*)d_in[8];
    const float* b2    = (const float*)d_in[9];
    const float* w_ih3 = (const float*)d_in[10];
    const float* w_hh3 = (const float*)d_in[11];
    const float* b3    = (const float*)d_in[12];
    const float* fc_w  = (const float*)d_in[13];
    const float* fc_b  = (const float*)d_in[14];
    float* out = (float*)d_out;

    dim3 ggrid(G4 / 128, S_LEN / 128);

    // layer 0
    gemm_xwt<<<ggrid, 256>>>(seq, 0, w_ih0, b0, 256);
    lstm_scan<<<128, 256>>>(w_hh0, 1, 0);   // -> g_yA
    // layer 1
    gemm_xwt<<<ggrid, 256>>>(nullptr, 1, w_ih1, b1, HID);
    lstm_scan<<<128, 256>>>(w_hh1, 2, 1);   // -> g_yB
    // layer 2
    gemm_xwt<<<ggrid, 256>>>(nullptr, 2, w_ih2, b2, HID);
    lstm_scan<<<128, 256>>>(w_hh2, 1, 2);   // -> g_yA
    // layer 3
    gemm_xwt<<<ggrid, 256>>>(nullptr, 1, w_ih3, b3, HID);
    lstm_scan<<<128, 256>>>(w_hh3, 2, 3);   // -> g_yB
    // head
    fc_kernel<<<1, 256>>>(fc_w, fc_b, out);
}